// round 5
// baseline (speedup 1.0000x reference)
#include <cuda_runtime.h>

// B=128, N=1024. out[b,k] = a[b,j] - a[b,i] over strict upper triangle (j>i),
// row-major pair order. Row i (i=0..1022) has len 1023-i and starts at
// off(i) = (i*(2047-i))/2.
//
// Work decomposition: pair row p with row 1022-p -> exactly 1024 outputs per
// pair. 8 pairs per block -> 8192 outputs per block, perfectly balanced,
// and the row index comes straight from blockIdx (no per-element index math).

constexpr int N_ELEM  = 1024;
constexpr int M_PAIRS = N_ELEM * (N_ELEM - 1) / 2;   // 523776
constexpr int THREADS = 256;
constexpr int PAIRS_PER_BLOCK = 8;                   // 512 pairs total -> grid.x = 64
constexpr int PITCH   = N_ELEM + 4;                  // 16B-aligned copy pitch

__device__ __forceinline__ int row_off(int i) {
    return (i * (2047 - i)) >> 1;                    // exact (product is even)
}

__device__ __forceinline__ void do_row(int i, const float* __restrict__ sh,
                                       float* __restrict__ outb) {
    const int start = row_off(i);
    const int len   = 1023 - i;
    const int end   = start + len;
    const float ai  = sh[i];                         // broadcast LDS
    const int t     = threadIdx.x;

    const int astart = (start + 3) & ~3;             // first 16B-aligned slot
    const int head   = astart - start;               // 0..3 leading scalars
    int n4 = (end - astart) >> 2;                    // aligned float4 count
    if (n4 < 0) n4 = 0;
    const int tail = end - astart - (n4 << 2);       // 0..3 trailing scalars

    // head scalars (<=3 lanes of warp 0)
    if (t < head && t < len)
        outb[start + t] = sh[i + 1 + t] - ai;

    // aligned bulk: one LDS.128 + STG.128 per lane
    if (t < n4) {
        const int pos = astart + (t << 2);
        const int j   = i + 1 + (pos - start);
        const int r   = j & 3;
        const float4 v = *reinterpret_cast<const float4*>(&sh[r * PITCH + (j - r)]);
        *reinterpret_cast<float4*>(outb + pos) =
            make_float4(v.x - ai, v.y - ai, v.z - ai, v.w - ai);
    }

    // tail scalars (<=3 lanes)
    if (t < tail) {
        const int pos = astart + (n4 << 2) + t;
        outb[pos] = sh[i + 1 + (pos - start)] - ai;
    }
}

__global__ __launch_bounds__(THREADS)
void relpos_kernel(const float* __restrict__ in, float* __restrict__ out) {
    // 4 shifted copies: sh[r*PITCH + m] = a[m + r]
    __shared__ float sh[4 * PITCH];

    const int b = blockIdx.y;
    const float* a = in + (size_t)b * N_ELEM;

    // Stage input + build shifted copies (one float4 per thread).
    {
        const float4 v = reinterpret_cast<const float4*>(a)[threadIdx.x];
        const int idx = threadIdx.x * 4;
        const float vv[4] = {v.x, v.y, v.z, v.w};
        #pragma unroll
        for (int e = 0; e < 4; e++) {
            const int x = idx + e;
            const float val = vv[e];
            #pragma unroll
            for (int r = 0; r < 4; r++) {
                const int m = x - r;
                if (m >= 0) sh[r * PITCH + m] = val;
            }
        }
    }
    __syncthreads();

    float* outb = out + (size_t)b * M_PAIRS;

    #pragma unroll
    for (int s = 0; s < PAIRS_PER_BLOCK; s++) {
        const int p = blockIdx.x * PAIRS_PER_BLOCK + s;  // pair index, 0..511
        do_row(p, sh, outb);                              // long row, len 1023-p
        if (p < 511)
            do_row(1022 - p, sh, outb);                   // short partner, len p+1
        // p == 511: middle row handled by the long call alone (len 512)
    }
}

extern "C" void kernel_launch(void* const* d_in, const int* in_sizes, int n_in,
                              void* d_out, int out_size) {
    const float* in = (const float*)d_in[0];
    float* out = (float*)d_out;
    const int B = in_sizes[0] / N_ELEM;   // 128

    dim3 grid(512 / PAIRS_PER_BLOCK, B);  // (64, 128)
    relpos_kernel<<<grid, THREADS>>>(in, out);
}